// round 1
// baseline (speedup 1.0000x reference)
#include <cuda_runtime.h>
#include <math.h>
#include <stdint.h>

// ---------------------------------------------------------------------------
// Problem constants (fixed by the reference)
// ---------------------------------------------------------------------------
namespace {
constexpr int Bb = 4;
constexpr int Ls = 2048;
constexpr int DM = 1024;          // d_model
constexpr int DS = 64;            // d_state
constexpr int DI = 2048;          // d_inner
constexpr int MR = Bb * Ls;       // 8192 flattened rows
constexpr int N1 = 2 * DI;        // 4096 (Wi output)
constexpr int ND = 2 * DS + DI;   // 2176 (Wx output)
}

// ---------------------------------------------------------------------------
// Scratch (device globals — no allocations allowed)
// ---------------------------------------------------------------------------
__device__ float g_xs[(size_t)MR * DI];     // silu(xs)
__device__ float g_rsil[(size_t)MR * DI];   // silu(res)
__device__ float g_xdbl[(size_t)MR * ND];   // xs @ Wx + bx
__device__ float g_delta[(size_t)MR * DI];  // softplus(d_raw @ Wdt + bdt)
__device__ float g_y[(size_t)MR * DI];      // scan output (post elementwise)

__device__ __forceinline__ float siluf(float v) {
    return v / (1.0f + __expf(-v));
}

// ---------------------------------------------------------------------------
// SGEMM: C[M,N] = A[M,K(lda)] @ B[K,N] (+ bias) with fused epilogues
// 128x128 block tile, BK=16, 256 threads, 8x8 per thread.
// ---------------------------------------------------------------------------
enum { EPI_SPLIT_SILU = 0, EPI_BIAS = 1, EPI_SOFTPLUS = 2, EPI_RESID = 3 };

template<int EPI>
__global__ __launch_bounds__(256, 2)
void sgemm_kernel(const float* __restrict__ A, const float* __restrict__ Bm,
                  const float* __restrict__ bias,
                  float* __restrict__ out, float* __restrict__ out2,
                  const float* __restrict__ resid,
                  int M, int N, int K, int lda, int ldc)
{
    constexpr int BM = 128, BN = 128, BK = 16, TM = 8, TN = 8;
    __shared__ float As[BK][BM];
    __shared__ float Bs[BK][BN];

    const int tid = threadIdx.x;
    const int tx = tid & 15;          // n direction (16)
    const int ty = tid >> 4;          // m direction (16)
    const int m0 = blockIdx.y * BM;
    const int n0 = blockIdx.x * BN;

    // A loader: 128 rows x 16 cols; thread -> (row = tid/4, 4 cols at (tid%4)*4)
    const int arow = tid >> 2;            // 0..63  (two passes: +0, +64)
    const int acol = (tid & 3) * 4;       // 0,4,8,12
    // B loader: 16 rows x 128 cols; thread -> (row = tid/32, 4 cols at (tid%32)*4)
    const int brow = tid >> 5;            // 0..7   (two passes: +0, +8)
    const int bcol = (tid & 31) * 4;

    float acc[TM][TN] = {};

    for (int k0 = 0; k0 < K; k0 += BK) {
        #pragma unroll
        for (int p = 0; p < 2; ++p) {
            int r = arow + p * 64;
            float4 v = *(const float4*)(A + (size_t)(m0 + r) * lda + k0 + acol);
            As[acol + 0][r] = v.x;
            As[acol + 1][r] = v.y;
            As[acol + 2][r] = v.z;
            As[acol + 3][r] = v.w;
        }
        #pragma unroll
        for (int p = 0; p < 2; ++p) {
            int r = brow + p * 8;
            *(float4*)(&Bs[r][bcol]) =
                *(const float4*)(Bm + (size_t)(k0 + r) * N + n0 + bcol);
        }
        __syncthreads();

        #pragma unroll
        for (int kk = 0; kk < BK; ++kk) {
            float4 a0 = *(const float4*)(&As[kk][ty * TM]);
            float4 a1 = *(const float4*)(&As[kk][ty * TM + 4]);
            float4 b0 = *(const float4*)(&Bs[kk][tx * TN]);
            float4 b1 = *(const float4*)(&Bs[kk][tx * TN + 4]);
            float ar[TM] = {a0.x, a0.y, a0.z, a0.w, a1.x, a1.y, a1.z, a1.w};
            float br[TN] = {b0.x, b0.y, b0.z, b0.w, b1.x, b1.y, b1.z, b1.w};
            #pragma unroll
            for (int i = 0; i < TM; ++i)
                #pragma unroll
                for (int j = 0; j < TN; ++j)
                    acc[i][j] = fmaf(ar[i], br[j], acc[i][j]);
        }
        __syncthreads();
    }

    const int row0 = m0 + ty * TM;
    const int col0 = n0 + tx * TN;
    #pragma unroll
    for (int i = 0; i < TM; ++i) {
        const int row = row0 + i;
        #pragma unroll
        for (int j = 0; j < TN; ++j) {
            const int col = col0 + j;
            float v = acc[i][j] + bias[col];
            if (EPI == EPI_SPLIT_SILU) {
                float s = siluf(v);
                if (col < DI) out[(size_t)row * DI + col] = s;
                else          out2[(size_t)row * DI + (col - DI)] = s;
            } else if (EPI == EPI_BIAS) {
                out[(size_t)row * ldc + col] = v;
            } else if (EPI == EPI_SOFTPLUS) {
                out[(size_t)row * ldc + col] =
                    (v > 20.0f) ? v : log1pf(__expf(v));
            } else { // EPI_RESID
                out[(size_t)row * ldc + col] =
                    v + resid[(size_t)row * ldc + col];
            }
        }
    }
}

// ---------------------------------------------------------------------------
// Selective scan: one warp per (b, d) channel; 2 states per lane.
// Fuses y = (y + xs*Dp) * silu(res) into the per-step output.
// ---------------------------------------------------------------------------
__global__ __launch_bounds__(256)
void scan_kernel(const float* __restrict__ A_log, const float* __restrict__ Dp)
{
    const int b    = blockIdx.y;
    const int warp = threadIdx.x >> 5;
    const int lane = threadIdx.x & 31;
    const int d    = blockIdx.x * 8 + warp;

    const float A0 = -__expf(A_log[d * DS + 2 * lane]);
    const float A1 = -__expf(A_log[d * DS + 2 * lane + 1]);
    const float dp = Dp[d];

    const float* dlt = g_delta + (size_t)b * Ls * DI + d;
    const float* xsp = g_xs    + (size_t)b * Ls * DI + d;
    const float* rsp = g_rsil  + (size_t)b * Ls * DI + d;
    const float* csp = g_xdbl  + (size_t)b * Ls * ND + 2 * DS + d;
    const float* bsp = g_xdbl  + (size_t)b * Ls * ND + DS;      // B_sel row
    float*       yp  = g_y     + (size_t)b * Ls * DI + d;

    float h0 = 0.0f, h1 = 0.0f;

    for (int l = 0; l < Ls; ++l) {
        const float  delta_t = dlt[(size_t)l * DI];
        const float  x_t     = xsp[(size_t)l * DI];
        const float  c_t     = csp[(size_t)l * ND];
        const float2 bb      = *(const float2*)(bsp + (size_t)l * ND + 2 * lane);

        const float dA0 = __expf(delta_t * A0);
        const float dA1 = __expf(delta_t * A1);
        const float dx  = delta_t * x_t;
        h0 = fmaf(dA0, h0, dx * bb.x);
        h1 = fmaf(dA1, h1, dx * bb.y);

        float s = h0 + h1;
        #pragma unroll
        for (int o = 16; o; o >>= 1)
            s += __shfl_xor_sync(0xffffffffu, s, o);

        if (lane == 0) {
            float y = c_t * s;
            y = (y + x_t * dp) * rsp[(size_t)l * DI];
            yp[(size_t)l * DI] = y;
        }
    }
}

// ---------------------------------------------------------------------------
// LayerNorm in-place over rows of DM=1024. One block (256 thr) per row.
// ---------------------------------------------------------------------------
__global__ __launch_bounds__(256)
void ln_kernel(float* __restrict__ io, const float* __restrict__ gamma,
               const float* __restrict__ beta)
{
    const int row = blockIdx.x;
    const int t = threadIdx.x;
    float* p = io + (size_t)row * DM;

    float4 v = reinterpret_cast<float4*>(p)[t];
    __shared__ float sred[8];

    float s = v.x + v.y + v.z + v.w;
    #pragma unroll
    for (int o = 16; o; o >>= 1) s += __shfl_xor_sync(0xffffffffu, s, o);
    if ((t & 31) == 0) sred[t >> 5] = s;
    __syncthreads();
    float mean = 0.0f;
    #pragma unroll
    for (int i = 0; i < 8; ++i) mean += sred[i];
    mean *= (1.0f / DM);
    __syncthreads();

    const float d0 = v.x - mean, d1 = v.y - mean, d2 = v.z - mean, d3 = v.w - mean;
    float q = d0 * d0 + d1 * d1 + d2 * d2 + d3 * d3;
    #pragma unroll
    for (int o = 16; o; o >>= 1) q += __shfl_xor_sync(0xffffffffu, q, o);
    if ((t & 31) == 0) sred[t >> 5] = q;
    __syncthreads();
    float var = 0.0f;
    #pragma unroll
    for (int i = 0; i < 8; ++i) var += sred[i];
    var *= (1.0f / DM);
    const float rstd = rsqrtf(var + 1e-5f);

    const float4 g  = reinterpret_cast<const float4*>(gamma)[t];
    const float4 bt = reinterpret_cast<const float4*>(beta)[t];
    float4 o4;
    o4.x = g.x * d0 * rstd + bt.x;
    o4.y = g.y * d1 * rstd + bt.y;
    o4.z = g.z * d2 * rstd + bt.z;
    o4.w = g.w * d3 * rstd + bt.w;
    reinterpret_cast<float4*>(p)[t] = o4;
}

// ---------------------------------------------------------------------------
// Launch
// ---------------------------------------------------------------------------
extern "C" void kernel_launch(void* const* d_in, const int* in_sizes, int n_in,
                              void* d_out, int out_size)
{
    (void)in_sizes; (void)n_in; (void)out_size;
    const float* x     = (const float*)d_in[0];
    const float* Wi    = (const float*)d_in[1];
    const float* bi    = (const float*)d_in[2];
    const float* Wx    = (const float*)d_in[3];
    const float* bx    = (const float*)d_in[4];
    const float* Wdt   = (const float*)d_in[5];
    const float* bdt   = (const float*)d_in[6];
    const float* A_log = (const float*)d_in[7];
    const float* Dp    = (const float*)d_in[8];
    const float* Wo    = (const float*)d_in[9];
    const float* bo    = (const float*)d_in[10];
    const float* gamma = (const float*)d_in[11];
    const float* beta  = (const float*)d_in[12];
    float* out = (float*)d_out;

    float *xs, *rsil, *xdbl, *delta, *y;
    cudaGetSymbolAddress((void**)&xs,    g_xs);
    cudaGetSymbolAddress((void**)&rsil,  g_rsil);
    cudaGetSymbolAddress((void**)&xdbl,  g_xdbl);
    cudaGetSymbolAddress((void**)&delta, g_delta);
    cudaGetSymbolAddress((void**)&y,     g_y);

    dim3 blk(256);

    // 1) x @ Wi + bi -> silu split into xs / silu(res)
    sgemm_kernel<EPI_SPLIT_SILU><<<dim3(N1 / 128, MR / 128), blk>>>(
        x, Wi, bi, xs, rsil, nullptr, MR, N1, DM, DM, 0);

    // 2) xs @ Wx + bx -> x_dbl
    sgemm_kernel<EPI_BIAS><<<dim3(ND / 128, MR / 128), blk>>>(
        xs, Wx, bx, xdbl, nullptr, nullptr, MR, ND, DI, DI, ND);

    // 3) softplus(d_raw @ Wdt + bdt) -> delta   (A = x_dbl[:, :64], lda = ND)
    sgemm_kernel<EPI_SOFTPLUS><<<dim3(DI / 128, MR / 128), blk>>>(
        xdbl, Wdt, bdt, delta, nullptr, nullptr, MR, DI, DS, ND, DI);

    // 4) selective scan + fused (y + xs*Dp) * silu(res)
    scan_kernel<<<dim3(DI / 8, Bb), 256>>>(A_log, Dp);

    // 5) y @ Wo + bo + residual -> d_out
    sgemm_kernel<EPI_RESID><<<dim3(DM / 128, MR / 128), blk>>>(
        y, Wo, bo, out, nullptr, x, MR, DM, DI, DI, DM);

    // 6) LayerNorm in place
    ln_kernel<<<MR, 256>>>(out, gamma, beta);
}

// round 5
// speedup vs baseline: 1.4622x; 1.4622x over previous
#include <cuda_runtime.h>
#include <cuda_fp16.h>
#include <math.h>
#include <stdint.h>

// ---------------------------------------------------------------------------
// Problem constants
// ---------------------------------------------------------------------------
namespace {
constexpr int Bb = 4;
constexpr int Ls = 2048;
constexpr int DM = 1024;          // d_model
constexpr int DS = 64;            // d_state
constexpr int DI = 2048;          // d_inner
constexpr int MR = Bb * Ls;       // 8192 rows
constexpr int N1 = 2 * DI;        // 4096
constexpr int ND = 2 * DS + DI;   // 2176  (= 17 * 128, block-aligned)
constexpr int NDP = 2304;         // Wx transpose padding
}

// ---------------------------------------------------------------------------
// Scratch (device globals — no allocations allowed)
// ---------------------------------------------------------------------------
__device__ float g_xs[(size_t)MR * DI];
__device__ float g_rsil[(size_t)MR * DI];
__device__ float g_xdbl[(size_t)MR * ND];
__device__ float g_delta[(size_t)MR * DI];

__device__ __half g_xhi[(size_t)MR * DM],  g_xlo[(size_t)MR * DM];
__device__ __half g_xshi[(size_t)MR * DI], g_xslo[(size_t)MR * DI];
__device__ __half g_yhi[(size_t)MR * DI],  g_ylo[(size_t)MR * DI];

__device__ __half g_Wihi[(size_t)N1 * DM],  g_Wilo[(size_t)N1 * DM];
__device__ __half g_Wxhi[(size_t)NDP * DI], g_Wxlo[(size_t)NDP * DI];
__device__ __half g_Wohi[(size_t)DM * DI],  g_Wolo[(size_t)DM * DI];

// ---------------------------------------------------------------------------
// Helpers
// ---------------------------------------------------------------------------
__device__ __forceinline__ float siluf(float v) {
    return v / (1.0f + __expf(-v));
}

__device__ __forceinline__ uint32_t smem_u32(const void* p) {
    uint32_t a;
    asm("{ .reg .u64 t; cvta.to.shared.u64 t, %1; cvt.u32.u64 %0, t; }"
        : "=r"(a) : "l"(p));
    return a;
}

#define LDSM4(R, A) \
    asm volatile("ldmatrix.sync.aligned.m8n8.x4.shared.b16 {%0,%1,%2,%3}, [%4];" \
        : "=r"((R)[0]), "=r"((R)[1]), "=r"((R)[2]), "=r"((R)[3]) : "r"(A))

#define MMA16816(C, A, B0, B1) \
    asm volatile("mma.sync.aligned.m16n8k16.row.col.f32.f16.f16.f32 " \
        "{%0,%1,%2,%3}, {%4,%5,%6,%7}, {%8,%9}, {%0,%1,%2,%3};" \
        : "+f"((C)[0]), "+f"((C)[1]), "+f"((C)[2]), "+f"((C)[3]) \
        : "r"((A)[0]), "r"((A)[1]), "r"((A)[2]), "r"((A)[3]), "r"(B0), "r"(B1))

#define CP_ASYNC16(dst, src) \
    asm volatile("cp.async.cg.shared.global [%0], [%1], 16;" :: "r"(dst), "l"(src))
#define CP_COMMIT()  asm volatile("cp.async.commit_group;" ::: "memory")
#define CP_WAIT(n)   asm volatile("cp.async.wait_group %0;" :: "n"(n) : "memory")

// ---------------------------------------------------------------------------
// cp.async one 128-row x 64-half (128B/row) tile, SW128 swizzle
// ---------------------------------------------------------------------------
__device__ __forceinline__ void cpa_tile(uint32_t dbase, const __half* __restrict__ src,
                                         int row0, int K, int k0, int tid)
{
    #pragma unroll
    for (int i = 0; i < 4; ++i) {
        const int ci  = tid + 256 * i;
        const int row = ci >> 3, ch = ci & 7;
        const __half* s = src + (size_t)(row0 + row) * K + k0 + ch * 8;
        const uint32_t d = dbase + (uint32_t)row * 128u
                         + (((uint32_t)ch ^ (uint32_t)(row & 7)) << 4);
        CP_ASYNC16(d, s);
    }
}

// ---------------------------------------------------------------------------
// HMMA GEMM: C[M,N] tile 128x128, BK=64 halves, fp16 hi/lo split, 3 passes.
// out = (Ahi+Alo) @ (Bhi+Blo)^T + bias, fused epilogues.
// ---------------------------------------------------------------------------
enum { EPI_G1 = 0, EPI_G2 = 1, EPI_G5 = 2 };

constexpr int HT_TILE  = 16384;            // one 128x128B tile
constexpr int HT_STAGE = 4 * HT_TILE;      // Ahi Alo Bhi Blo
constexpr int HT_SMEM  = 2 * HT_STAGE + 1024;

template<int EPI>
__global__ __launch_bounds__(256, 1)
void hmma_gemm(const __half* __restrict__ Ahi, const __half* __restrict__ Alo,
               const __half* __restrict__ Bhi, const __half* __restrict__ Blo,
               const float* __restrict__ bias,
               float* __restrict__ o_f32,           // xs / xdbl / out
               float* __restrict__ o_f32b,          // rsil (G1)
               __half* __restrict__ o_hi, __half* __restrict__ o_lo,
               const float* __restrict__ resid,     // x (G5)
               int K)
{
    extern __shared__ char smem[];
    const int tid = threadIdx.x, wid = tid >> 5, lane = tid & 31;
    const int wm = wid & 3, wn = wid >> 2;
    const int m0 = blockIdx.y * 128, n0 = blockIdx.x * 128;

    const uint32_t sb = (smem_u32(smem) + 1023u) & ~1023u;

    const int T = K >> 6;

    // prologue: stage 0
    cpa_tile(sb + 0 * HT_TILE, Ahi, m0, K, 0, tid);
    cpa_tile(sb + 1 * HT_TILE, Alo, m0, K, 0, tid);
    cpa_tile(sb + 2 * HT_TILE, Bhi, n0, K, 0, tid);
    cpa_tile(sb + 3 * HT_TILE, Blo, n0, K, 0, tid);
    CP_COMMIT();

    float c[2][8][4];
    #pragma unroll
    for (int mi = 0; mi < 2; ++mi)
        #pragma unroll
        for (int j = 0; j < 8; ++j)
            #pragma unroll
            for (int q = 0; q < 4; ++q) c[mi][j][q] = 0.0f;

    // ldmatrix lane addressing
    const int arow_l  = lane & 15;          // A: lanes 0-15 rows, 16-31 k+8
    const int achunk  = lane >> 4;
    const int brow_l  = (lane & 7) | ((lane & 16) >> 1);  // B: n rows
    const int bchunk  = (lane >> 3) & 1;

    const int rowA0 = wm * 32 + arow_l;     // mi=0
    const int rowA1 = rowA0 + 16;           // mi=1

    #pragma unroll 1
    for (int t = 0; t < T; ++t) {
        if (t + 1 < T) {
            const uint32_t stb = sb + ((t + 1) & 1) * HT_STAGE;
            const int k0 = (t + 1) * 64;
            cpa_tile(stb + 0 * HT_TILE, Ahi, m0, K, k0, tid);
            cpa_tile(stb + 1 * HT_TILE, Alo, m0, K, k0, tid);
            cpa_tile(stb + 2 * HT_TILE, Bhi, n0, K, k0, tid);
            cpa_tile(stb + 3 * HT_TILE, Blo, n0, K, k0, tid);
            CP_COMMIT();
            CP_WAIT(1);
        } else {
            CP_WAIT(0);
        }
        __syncthreads();

        const uint32_t stb = sb + (t & 1) * HT_STAGE;
        const uint32_t sAh = stb, sAl = stb + HT_TILE;
        const uint32_t sBh = stb + 2 * HT_TILE, sBl = stb + 3 * HT_TILE;

        #pragma unroll
        for (int ks = 0; ks < 4; ++ks) {
            uint32_t ah[2][4], al[2][4], bh[4][4], bl[4][4];
            {
                const uint32_t off0 = (uint32_t)rowA0 * 128u
                    + ((uint32_t)((2 * ks + achunk) ^ (rowA0 & 7)) << 4);
                const uint32_t off1 = (uint32_t)rowA1 * 128u
                    + ((uint32_t)((2 * ks + achunk) ^ (rowA1 & 7)) << 4);
                LDSM4(ah[0], sAh + off0);
                LDSM4(al[0], sAl + off0);
                LDSM4(ah[1], sAh + off1);
                LDSM4(al[1], sAl + off1);
            }
            #pragma unroll
            for (int bj = 0; bj < 4; ++bj) {
                const int rowB = wn * 64 + bj * 16 + brow_l;
                const uint32_t off = (uint32_t)rowB * 128u
                    + ((uint32_t)((2 * ks + bchunk) ^ (rowB & 7)) << 4);
                LDSM4(bh[bj], sBh + off);
                LDSM4(bl[bj], sBl + off);
            }
            #pragma unroll
            for (int mi = 0; mi < 2; ++mi)
                #pragma unroll
                for (int j = 0; j < 8; ++j) {
                    const uint32_t bh0 = bh[j >> 1][(j & 1) * 2];
                    const uint32_t bh1 = bh[j >> 1][(j & 1) * 2 + 1];
                    const uint32_t bl0 = bl[j >> 1][(j & 1) * 2];
                    const uint32_t bl1 = bl[j >> 1][(j & 1) * 2 + 1];
                    MMA16816(c[mi][j], ah[mi], bh0, bh1);   // hh
                    MMA16816(c[mi][j], ah[mi], bl0, bl1);   // hl
                    MMA16816(c[mi][j], al[mi], bh0, bh1);   // lh
                }
        }
        __syncthreads();
    }

    // ---------------- epilogue
    const int qrow = lane >> 2, qcol = (lane & 3) * 2;

    #pragma unroll
    for (int mi = 0; mi < 2; ++mi)
        #pragma unroll
        for (int r = 0; r < 2; ++r) {
            const int row = m0 + wm * 32 + mi * 16 + qrow + r * 8;
            #pragma unroll
            for (int j = 0; j < 8; ++j) {
                const int col = n0 + wn * 64 + j * 8 + qcol;
                const float2 b2 = *reinterpret_cast<const float2*>(bias + col);
                float v0 = c[mi][j][2 * r]     + b2.x;
                float v1 = c[mi][j][2 * r + 1] + b2.y;

                if (EPI == EPI_G1) {
                    v0 = siluf(v0); v1 = siluf(v1);
                    if (n0 < DI) {       // xs half
                        const size_t base = (size_t)row * DI + col;
                        *reinterpret_cast<float2*>(o_f32 + base) = make_float2(v0, v1);
                        const __half h0 = __float2half_rn(v0);
                        const __half h1 = __float2half_rn(v1);
                        const __half l0 = __float2half_rn(v0 - __half2float(h0));
                        const __half l1 = __float2half_rn(v1 - __half2float(h1));
                        *reinterpret_cast<__half2*>(o_hi + base) = __halves2half2(h0, h1);
                        *reinterpret_cast<__half2*>(o_lo + base) = __halves2half2(l0, l1);
                    } else {             // silu(res)
                        const size_t base = (size_t)row * DI + (col - DI);
                        *reinterpret_cast<float2*>(o_f32b + base) = make_float2(v0, v1);
                    }
                } else if (EPI == EPI_G2) {
                    const size_t base = (size_t)row * ND + col;
                    *reinterpret_cast<float2*>(o_f32 + base) = make_float2(v0, v1);
                } else {                 // EPI_G5
                    const size_t base = (size_t)row * DM + col;
                    const float2 rx = *reinterpret_cast<const float2*>(resid + base);
                    *reinterpret_cast<float2*>(o_f32 + base) =
                        make_float2(v0 + rx.x, v1 + rx.y);
                }
            }
        }
}

// ---------------------------------------------------------------------------
// fp32 -> fp16 hi/lo split
// ---------------------------------------------------------------------------
__global__ __launch_bounds__(256)
void convert_split(const float* __restrict__ in,
                   __half* __restrict__ oh, __half* __restrict__ ol, size_t n4)
{
    const size_t i = (size_t)blockIdx.x * blockDim.x + threadIdx.x;
    if (i >= n4) return;
    const float4 v = reinterpret_cast<const float4*>(in)[i];
    const float a[4] = {v.x, v.y, v.z, v.w};
    __half h[4], l[4];
    #pragma unroll
    for (int s = 0; s < 4; ++s) {
        h[s] = __float2half_rn(a[s]);
        l[s] = __float2half_rn(a[s] - __half2float(h[s]));
    }
    reinterpret_cast<__half2*>(oh)[2 * i]     = __halves2half2(h[0], h[1]);
    reinterpret_cast<__half2*>(oh)[2 * i + 1] = __halves2half2(h[2], h[3]);
    reinterpret_cast<__half2*>(ol)[2 * i]     = __halves2half2(l[0], l[1]);
    reinterpret_cast<__half2*>(ol)[2 * i + 1] = __halves2half2(l[2], l[3]);
}

// ---------------------------------------------------------------------------
// Weight transpose + split: W[K][Nreal] f32 -> Wt_hi/lo[Npad][K] fp16
// ---------------------------------------------------------------------------
__global__ __launch_bounds__(256)
void transpose_split(const float* __restrict__ W,
                     __half* __restrict__ Th, __half* __restrict__ Tl,
                     int K, int Nreal)
{
    __shared__ float s[32][33];
    const int n0 = blockIdx.x * 32, k0 = blockIdx.y * 32;
    const int tx = threadIdx.x, ty = threadIdx.y;   // 32 x 8
    #pragma unroll
    for (int i = 0; i < 32; i += 8) {
        const int k = k0 + ty + i, n = n0 + tx;
        s[ty + i][tx] = (n < Nreal) ? W[(size_t)k * Nreal + n] : 0.0f;
    }
    __syncthreads();
    #pragma unroll
    for (int i = 0; i < 32; i += 8) {
        const int n = n0 + ty + i, k = k0 + tx;
        const float v = s[tx][ty + i];
        const __half h = __float2half_rn(v);
        Th[(size_t)n * K + k] = h;
        Tl[(size_t)n * K + k] = __float2half_rn(v - __half2float(h));
    }
}

// ---------------------------------------------------------------------------
// FFMA SGEMM with softplus (delta: K=64)
// ---------------------------------------------------------------------------
__global__ __launch_bounds__(256, 2)
void sgemm_softplus(const float* __restrict__ A, const float* __restrict__ Bm,
                    const float* __restrict__ bias, float* __restrict__ out,
                    int M, int N, int K, int lda, int ldc)
{
    constexpr int BM = 128, BN = 128, BK = 16, TM = 8, TN = 8;
    __shared__ float As[BK][BM];
    __shared__ float Bs[BK][BN];

    const int tid = threadIdx.x;
    const int tx = tid & 15, ty = tid >> 4;
    const int m0 = blockIdx.y * BM, n0 = blockIdx.x * BN;
    const int arow = tid >> 2, acol = (tid & 3) * 4;
    const int brow = tid >> 5, bcol = (tid & 31) * 4;

    float acc[TM][TN] = {};
    for (int k0 = 0; k0 < K; k0 += BK) {
        #pragma unroll
        for (int p = 0; p < 2; ++p) {
            int r = arow + p * 64;
            float4 v = *(const float4*)(A + (size_t)(m0 + r) * lda + k0 + acol);
            As[acol + 0][r] = v.x; As[acol + 1][r] = v.y;
            As[acol + 2][r] = v.z; As[acol + 3][r] = v.w;
        }
        #pragma unroll
        for (int p = 0; p < 2; ++p) {
            int r = brow + p * 8;
            *(float4*)(&Bs[r][bcol]) = *(const float4*)(Bm + (size_t)(k0 + r) * N + n0 + bcol);
        }
        __syncthreads();
        #pragma unroll
        for (int kk = 0; kk < BK; ++kk) {
            float4 a0 = *(const float4*)(&As[kk][ty * TM]);
            float4 a1 = *(const float4*)(&As[kk][ty * TM + 4]);
            float4 b0 = *(const float4*)(&Bs[kk][tx * TN]);
            float4 b1 = *(const float4*)(&Bs[kk][tx * TN + 4]);
            float ar[TM] = {a0.x, a0.y, a0.z, a0.w, a1.x, a1.y, a1.z, a1.w};
            float br[TN] = {b0.x, b0.y, b0.z, b0.w, b1.x, b1.y, b1.z, b1.w};
            #pragma unroll
            for (int i = 0; i < TM; ++i)
                #pragma unroll
                for (int j = 0; j < TN; ++j)
                    acc[i][j] = fmaf(ar[i], br[j], acc[i][j]);
        }
        __syncthreads();
    }
    const int row0 = m0 + ty * TM, col0 = n0 + tx * TN;
    #pragma unroll
    for (int i = 0; i < TM; ++i)
        #pragma unroll
        for (int j = 0; j < TN; ++j) {
            float v = acc[i][j] + bias[col0 + j];
            out[(size_t)(row0 + i) * ldc + col0 + j] =
                (v > 20.0f) ? v : log1pf(__expf(v));
        }
}

// ---------------------------------------------------------------------------
// Selective scan: one warp per (b, d); 2 states/lane; fused gating epilogue.
// Writes y as fp16 hi/lo (consumed only by G5 HMMA GEMM).
// ---------------------------------------------------------------------------
__global__ __launch_bounds__(256)
void scan_kernel(const float* __restrict__ A_log, const float* __restrict__ Dp)
{
    const int b    = blockIdx.y;
    const int warp = threadIdx.x >> 5;
    const int lane = threadIdx.x & 31;
    const int d    = blockIdx.x * 8 + warp;

    const float A0 = -__expf(A_log[d * DS + 2 * lane]);
    const float A1 = -__expf(A_log[d * DS + 2 * lane + 1]);
    const float dp = Dp[d];

    const float* dlt = g_delta + (size_t)b * Ls * DI + d;
    const float* xsp = g_xs    + (size_t)b * Ls * DI + d;
    const float* rsp = g_rsil  + (size_t)b * Ls * DI + d;
    const float* csp = g_xdbl  + (size_t)b * Ls * ND + 2 * DS + d;
    const float* bsp = g_xdbl  + (size_t)b * Ls * ND + DS;
    __half* yh = g_yhi + (size_t)b * Ls * DI + d;
    __half* yl = g_ylo + (size_t)b * Ls * DI + d;

    float h0 = 0.0f, h1 = 0.0f;
    for (int l = 0; l < Ls; ++l) {
        const float  delta_t = dlt[(size_t)l * DI];
        const float  x_t     = xsp[(size_t)l * DI];
        const float  c_t     = csp[(size_t)l * ND];
        const float2 bb      = *(const float2*)(bsp + (size_t)l * ND + 2 * lane);

        const float dA0 = __expf(delta_t * A0);
        const float dA1 = __expf(delta_t * A1);
        const float dx  = delta_t * x_t;
        h0 = fmaf(dA0, h0, dx * bb.x);
        h1 = fmaf(dA1, h1, dx * bb.y);

        float s = h0 + h1;
        #pragma unroll
        for (int o = 16; o; o >>= 1) s += __shfl_xor_sync(0xffffffffu, s, o);

        if (lane == 0) {
            float y = c_t * s;
            y = (y + x_t * dp) * rsp[(size_t)l * DI];
            const __half h = __float2half_rn(y);
            yh[(size_t)l * DI] = h;
            yl[(size_t)l * DI] = __float2half_rn(y - __half2float(h));
        }
    }
}

// ---------------------------------------------------------------------------
// LayerNorm in place (rows of DM)
// ---------------------------------------------------------------------------
__global__ __launch_bounds__(256)
void ln_kernel(float* __restrict__ io, const float* __restrict__ gamma,
               const float* __restrict__ beta)
{
    const int row = blockIdx.x;
    const int t = threadIdx.x;
    float* p = io + (size_t)row * DM;

    float4 v = reinterpret_cast<float4*>(p)[t];
    __shared__ float sred[8];

    float s = v.x + v.y + v.z + v.w;
    #pragma unroll
    for (int o = 16; o; o >>= 1) s += __shfl_xor_sync(0xffffffffu, s, o);
    if ((t & 31) == 0) sred[t >> 5] = s;
    __syncthreads();
    float mean = 0.0f;
    #pragma unroll
    for (int i = 0; i < 8; ++i) mean += sred[i];
    mean *= (1.0f / DM);
    __syncthreads();

    const float d0 = v.x - mean, d1 = v.y - mean, d2 = v.z - mean, d3 = v.w - mean;
    float q = d0 * d0 + d1 * d1 + d2 * d2 + d3 * d3;
    #pragma unroll
    for (int o = 16; o; o >>= 1) q += __shfl_xor_sync(0xffffffffu, q, o);
    if ((t & 31) == 0) sred[t >> 5] = q;
    __syncthreads();
    float var = 0.0f;
    #pragma unroll
    for (int i = 0; i < 8; ++i) var += sred[i];
    var *= (1.0f / DM);
    const float rstd = rsqrtf(var + 1e-5f);

    const float4 g  = reinterpret_cast<const float4*>(gamma)[t];
    const float4 bt = reinterpret_cast<const float4*>(beta)[t];
    float4 o4;
    o4.x = g.x * d0 * rstd + bt.x;
    o4.y = g.y * d1 * rstd + bt.y;
    o4.z = g.z * d2 * rstd + bt.z;
    o4.w = g.w * d3 * rstd + bt.w;
    reinterpret_cast<float4*>(p)[t] = o4;
}

// ---------------------------------------------------------------------------
// Launch
// ---------------------------------------------------------------------------
extern "C" void kernel_launch(void* const* d_in, const int* in_sizes, int n_in,
                              void* d_out, int out_size)
{
    (void)in_sizes; (void)n_in; (void)out_size;
    const float* x     = (const float*)d_in[0];
    const float* Wi    = (const float*)d_in[1];
    const float* bi    = (const float*)d_in[2];
    const float* Wx    = (const float*)d_in[3];
    const float* bx    = (const float*)d_in[4];
    const float* Wdt   = (const float*)d_in[5];
    const float* bdt   = (const float*)d_in[6];
    const float* A_log = (const float*)d_in[7];
    const float* Dp    = (const float*)d_in[8];
    const float* Wo    = (const float*)d_in[9];
    const float* bo    = (const float*)d_in[10];
    const float* gamma = (const float*)d_in[11];
    const float* beta  = (const float*)d_in[12];
    float* out = (float*)d_out;

    float *xs, *rsil, *xdbl, *delta;
    __half *xhi, *xlo, *xshi, *xslo, *yhi, *ylo;
    __half *Wihi, *Wilo, *Wxhi, *Wxlo, *Wohi, *Wolo;
    cudaGetSymbolAddress((void**)&xs,    g_xs);
    cudaGetSymbolAddress((void**)&rsil,  g_rsil);
    cudaGetSymbolAddress((void**)&xdbl,  g_xdbl);
    cudaGetSymbolAddress((void**)&delta, g_delta);
    cudaGetSymbolAddress((void**)&xhi,   g_xhi);
    cudaGetSymbolAddress((void**)&xlo,   g_xlo);
    cudaGetSymbolAddress((void**)&xshi,  g_xshi);
    cudaGetSymbolAddress((void**)&xslo,  g_xslo);
    cudaGetSymbolAddress((void**)&yhi,   g_yhi);
    cudaGetSymbolAddress((void**)&ylo,   g_ylo);
    cudaGetSymbolAddress((void**)&Wihi,  g_Wihi);
    cudaGetSymbolAddress((void**)&Wilo,  g_Wilo);
    cudaGetSymbolAddress((void**)&Wxhi,  g_Wxhi);
    cudaGetSymbolAddress((void**)&Wxlo,  g_Wxlo);
    cudaGetSymbolAddress((void**)&Wohi,  g_Wohi);
    cudaGetSymbolAddress((void**)&Wolo,  g_Wolo);

    cudaFuncSetAttribute(hmma_gemm<EPI_G1>, cudaFuncAttributeMaxDynamicSharedMemorySize, HT_SMEM);
    cudaFuncSetAttribute(hmma_gemm<EPI_G2>, cudaFuncAttributeMaxDynamicSharedMemorySize, HT_SMEM);
    cudaFuncSetAttribute(hmma_gemm<EPI_G5>, cudaFuncAttributeMaxDynamicSharedMemorySize, HT_SMEM);

    // ---- prep: split x, transpose+split weights
    {
        const size_t n4 = (size_t)MR * DM / 4;
        convert_split<<<(unsigned)((n4 + 255) / 256), 256>>>(x, xhi, xlo, n4);
    }
    transpose_split<<<dim3(N1 / 32,  DM / 32), dim3(32, 8)>>>(Wi, Wihi, Wilo, DM, N1);
    transpose_split<<<dim3(NDP / 32, DI / 32), dim3(32, 8)>>>(Wx, Wxhi, Wxlo, DI, ND);
    transpose_split<<<dim3(DM / 32,  DI / 32), dim3(32, 8)>>>(Wo, Wohi, Wolo, DI, DM);

    // ---- G1: x @ Wi + bi -> silu, split xs(+fp16 hi/lo) / silu(res)
    hmma_gemm<EPI_G1><<<dim3(N1 / 128, MR / 128), 256, HT_SMEM>>>(
        xhi, xlo, Wihi, Wilo, bi, xs, rsil, xshi, xslo, nullptr, DM);

    // ---- G2: xs @ Wx + bx -> x_dbl  (17 column blocks cover ND exactly)
    hmma_gemm<EPI_G2><<<dim3(ND / 128, MR / 128), 256, HT_SMEM>>>(
        xshi, xslo, Wxhi, Wxlo, bx, xdbl, nullptr, nullptr, nullptr, nullptr, DI);

    // ---- G3: softplus(d_raw @ Wdt + bdt) (K=64, FFMA)
    sgemm_softplus<<<dim3(DI / 128, MR / 128), 256>>>(
        xdbl, Wdt, bdt, delta, MR, DI, DS, ND, DI);

    // ---- scan + gating (fp16 hi/lo y)
    scan_kernel<<<dim3(DI / 8, Bb), 256>>>(A_log, Dp);

    // ---- G5: y @ Wo + bo + residual
    hmma_gemm<EPI_G5><<<dim3(DM / 128, MR / 128), 256, HT_SMEM>>>(
        yhi, ylo, Wohi, Wolo, bo, out, nullptr, nullptr, nullptr, x, DI);

    // ---- LayerNorm
    ln_kernel<<<MR, 256>>>(out, gamma, beta);
}

// round 7
// speedup vs baseline: 1.5247x; 1.0427x over previous
#include <cuda_runtime.h>
#include <cuda_fp16.h>
#include <math.h>
#include <stdint.h>

// ---------------------------------------------------------------------------
// Problem constants
// ---------------------------------------------------------------------------
namespace {
constexpr int Bb = 4;
constexpr int Ls = 2048;
constexpr int DM = 1024;          // d_model
constexpr int DS = 64;            // d_state
constexpr int DI = 2048;          // d_inner
constexpr int MR = Bb * Ls;       // 8192 rows
constexpr int N1 = 2 * DI;        // 4096
constexpr int ND = 2 * DS + DI;   // 2176  (= 17 * 128)
constexpr int NDP = 2304;         // Wx transpose padding
}

// ---------------------------------------------------------------------------
// Scratch (device globals — no allocations allowed)
// ---------------------------------------------------------------------------
__device__ float g_xs[(size_t)MR * DI];
__device__ float g_rsil[(size_t)MR * DI];
__device__ float g_xdbl[(size_t)MR * ND];
__device__ float g_delta[(size_t)MR * DI];

__device__ __half g_xhi[(size_t)MR * DM],  g_xlo[(size_t)MR * DM];
__device__ __half g_xshi[(size_t)MR * DI], g_xslo[(size_t)MR * DI];
__device__ __half g_yhi[(size_t)MR * DI],  g_ylo[(size_t)MR * DI];

__device__ __half g_Wihi[(size_t)N1 * DM],  g_Wilo[(size_t)N1 * DM];
__device__ __half g_Wxhi[(size_t)NDP * DI], g_Wxlo[(size_t)NDP * DI];
__device__ __half g_Wohi[(size_t)DM * DI],  g_Wolo[(size_t)DM * DI];

// ---------------------------------------------------------------------------
// Helpers
// ---------------------------------------------------------------------------
__device__ __forceinline__ float siluf(float v) {
    return v / (1.0f + __expf(-v));
}

__device__ __forceinline__ uint32_t smem_u32(const void* p) {
    uint32_t a;
    asm("{ .reg .u64 t; cvta.to.shared.u64 t, %1; cvt.u32.u64 %0, t; }"
        : "=r"(a) : "l"(p));
    return a;
}

#define LDSM4(R, A) \
    asm volatile("ldmatrix.sync.aligned.m8n8.x4.shared.b16 {%0,%1,%2,%3}, [%4];" \
        : "=r"((R)[0]), "=r"((R)[1]), "=r"((R)[2]), "=r"((R)[3]) : "r"(A))

#define MMA16816(C, A, B0, B1) \
    asm volatile("mma.sync.aligned.m16n8k16.row.col.f32.f16.f16.f32 " \
        "{%0,%1,%2,%3}, {%4,%5,%6,%7}, {%8,%9}, {%0,%1,%2,%3};" \
        : "+f"((C)[0]), "+f"((C)[1]), "+f"((C)[2]), "+f"((C)[3]) \
        : "r"((A)[0]), "r"((A)[1]), "r"((A)[2]), "r"((A)[3]), "r"(B0), "r"(B1))

#define CP_ASYNC16(dst, src) \
    asm volatile("cp.async.cg.shared.global [%0], [%1], 16;" :: "r"(dst), "l"(src))
#define CP_COMMIT()  asm volatile("cp.async.commit_group;" ::: "memory")
#define CP_WAIT(n)   asm volatile("cp.async.wait_group %0;" :: "n"(n) : "memory")

// ---------------------------------------------------------------------------
// cp.async NROWS x 64-half (128B/row) tile with SW128 swizzle
// ---------------------------------------------------------------------------
template<int NROWS>
__device__ __forceinline__ void cpa_tile(uint32_t dbase, const __half* __restrict__ src,
                                         int row0, int K, int k0, int tid)
{
    #pragma unroll
    for (int i = 0; i < NROWS / 32; ++i) {
        const int ci  = tid + 256 * i;
        const int row = ci >> 3, ch = ci & 7;
        const __half* s = src + (size_t)(row0 + row) * K + k0 + ch * 8;
        const uint32_t d = dbase + (uint32_t)row * 128u
                         + (((uint32_t)ch ^ (uint32_t)(row & 7)) << 4);
        CP_ASYNC16(d, s);
    }
}

// ---------------------------------------------------------------------------
// HMMA GEMM: C[M,N] tile 64x128, BK=64 halves, fp16 hi/lo split, 3 passes.
// 2 CTAs/SM (96KB smem each). out = (Ahi+Alo)@(Bhi+Blo)^T + bias, fused epi.
// ---------------------------------------------------------------------------
enum { EPI_G1 = 0, EPI_G2 = 1, EPI_G5 = 2 };

constexpr int HT_A     = 8192;               // 64 x 128B
constexpr int HT_B     = 16384;              // 128 x 128B
constexpr int HT_STAGE = 2 * HT_A + 2 * HT_B;  // 49152
constexpr int HT_SMEM  = 2 * HT_STAGE + 1024;  // 99328

template<int EPI>
__global__ __launch_bounds__(256, 2)
void hmma_gemm(const __half* __restrict__ Ahi, const __half* __restrict__ Alo,
               const __half* __restrict__ Bhi, const __half* __restrict__ Blo,
               const float* __restrict__ bias,
               float* __restrict__ o_f32,           // xs / xdbl / out
               float* __restrict__ o_f32b,          // rsil (G1)
               __half* __restrict__ o_hi, __half* __restrict__ o_lo,
               const float* __restrict__ resid,     // x (G5)
               int K)
{
    extern __shared__ char smem[];
    const int tid = threadIdx.x, wid = tid >> 5, lane = tid & 31;
    const int wm = wid & 1, wn = wid >> 1;       // 2 x 4 warp grid (32x32 each)
    const int m0 = blockIdx.y * 64, n0 = blockIdx.x * 128;

    const uint32_t sb = (smem_u32(smem) + 1023u) & ~1023u;

    const int T = K >> 6;

    // prologue: stage 0
    cpa_tile< 64>(sb + 0 * HT_A,          Ahi, m0, K, 0, tid);
    cpa_tile< 64>(sb + 1 * HT_A,          Alo, m0, K, 0, tid);
    cpa_tile<128>(sb + 2 * HT_A,          Bhi, n0, K, 0, tid);
    cpa_tile<128>(sb + 2 * HT_A + HT_B,   Blo, n0, K, 0, tid);
    CP_COMMIT();

    float c[2][4][4];
    #pragma unroll
    for (int mi = 0; mi < 2; ++mi)
        #pragma unroll
        for (int j = 0; j < 4; ++j)
            #pragma unroll
            for (int q = 0; q < 4; ++q) c[mi][j][q] = 0.0f;

    // ldmatrix lane addressing
    const int arow_l  = lane & 15;
    const int achunk  = lane >> 4;
    const int brow_l  = (lane & 7) | ((lane & 16) >> 1);
    const int bchunk  = (lane >> 3) & 1;

    const int rowA0 = wm * 32 + arow_l;
    const int rowA1 = rowA0 + 16;

    #pragma unroll 1
    for (int t = 0; t < T; ++t) {
        if (t + 1 < T) {
            const uint32_t stb = sb + ((t + 1) & 1) * HT_STAGE;
            const int k0 = (t + 1) * 64;
            cpa_tile< 64>(stb + 0 * HT_A,        Ahi, m0, K, k0, tid);
            cpa_tile< 64>(stb + 1 * HT_A,        Alo, m0, K, k0, tid);
            cpa_tile<128>(stb + 2 * HT_A,        Bhi, n0, K, k0, tid);
            cpa_tile<128>(stb + 2 * HT_A + HT_B, Blo, n0, K, k0, tid);
            CP_COMMIT();
            CP_WAIT(1);
        } else {
            CP_WAIT(0);
        }
        __syncthreads();

        const uint32_t stb = sb + (t & 1) * HT_STAGE;
        const uint32_t sAh = stb, sAl = stb + HT_A;
        const uint32_t sBh = stb + 2 * HT_A, sBl = stb + 2 * HT_A + HT_B;

        #pragma unroll
        for (int ks = 0; ks < 4; ++ks) {
            uint32_t ah[2][4], al[2][4], bh[2][4], bl[2][4];
            {
                const uint32_t off0 = (uint32_t)rowA0 * 128u
                    + ((uint32_t)((2 * ks + achunk) ^ (rowA0 & 7)) << 4);
                const uint32_t off1 = (uint32_t)rowA1 * 128u
                    + ((uint32_t)((2 * ks + achunk) ^ (rowA1 & 7)) << 4);
                LDSM4(ah[0], sAh + off0);
                LDSM4(al[0], sAl + off0);
                LDSM4(ah[1], sAh + off1);
                LDSM4(al[1], sAl + off1);
            }
            #pragma unroll
            for (int bj = 0; bj < 2; ++bj) {
                const int rowB = wn * 32 + bj * 16 + brow_l;
                const uint32_t off = (uint32_t)rowB * 128u
                    + ((uint32_t)((2 * ks + bchunk) ^ (rowB & 7)) << 4);
                LDSM4(bh[bj], sBh + off);
                LDSM4(bl[bj], sBl + off);
            }
            #pragma unroll
            for (int mi = 0; mi < 2; ++mi)
                #pragma unroll
                for (int j = 0; j < 4; ++j) {
                    const uint32_t bh0 = bh[j >> 1][(j & 1) * 2];
                    const uint32_t bh1 = bh[j >> 1][(j & 1) * 2 + 1];
                    const uint32_t bl0 = bl[j >> 1][(j & 1) * 2];
                    const uint32_t bl1 = bl[j >> 1][(j & 1) * 2 + 1];
                    MMA16816(c[mi][j], ah[mi], bh0, bh1);   // hh
                    MMA16816(c[mi][j], ah[mi], bl0, bl1);   // hl
                    MMA16816(c[mi][j], al[mi], bh0, bh1);   // lh
                }
        }
        __syncthreads();
    }

    // ---------------- epilogue
    const int qrow = lane >> 2, qcol = (lane & 3) * 2;

    #pragma unroll
    for (int mi = 0; mi < 2; ++mi)
        #pragma unroll
        for (int r = 0; r < 2; ++r) {
            const int row = m0 + wm * 32 + mi * 16 + qrow + r * 8;
            #pragma unroll
            for (int j = 0; j < 4; ++j) {
                const int col = n0 + wn * 32 + j * 8 + qcol;
                const float2 b2 = *reinterpret_cast<const float2*>(bias + col);
                float v0 = c[mi][j][2 * r]     + b2.x;
                float v1 = c[mi][j][2 * r + 1] + b2.y;

                if (EPI == EPI_G1) {
                    v0 = siluf(v0); v1 = siluf(v1);
                    if (n0 < DI) {       // xs half
                        const size_t base = (size_t)row * DI + col;
                        *reinterpret_cast<float2*>(o_f32 + base) = make_float2(v0, v1);
                        const __half h0 = __float2half_rn(v0);
                        const __half h1 = __float2half_rn(v1);
                        const __half l0 = __float2half_rn(v0 - __half2float(h0));
                        const __half l1 = __float2half_rn(v1 - __half2float(h1));
                        *reinterpret_cast<__half2*>(o_hi + base) = __halves2half2(h0, h1);
                        *reinterpret_cast<__half2*>(o_lo + base) = __halves2half2(l0, l1);
                    } else {             // silu(res)
                        const size_t base = (size_t)row * DI + (col - DI);
                        *reinterpret_cast<float2*>(o_f32b + base) = make_float2(v0, v1);
                    }
                } else if (EPI == EPI_G2) {
                    const size_t base = (size_t)row * ND + col;
                    *reinterpret_cast<float2*>(o_f32 + base) = make_float2(v0, v1);
                } else {                 // EPI_G5
                    const size_t base = (size_t)row * DM + col;
                    const float2 rx = *reinterpret_cast<const float2*>(resid + base);
                    *reinterpret_cast<float2*>(o_f32 + base) =
                        make_float2(v0 + rx.x, v1 + rx.y);
                }
            }
        }
}

// ---------------------------------------------------------------------------
// fp32 -> fp16 hi/lo split
// ---------------------------------------------------------------------------
__global__ __launch_bounds__(256)
void convert_split(const float* __restrict__ in,
                   __half* __restrict__ oh, __half* __restrict__ ol, size_t n4)
{
    const size_t i = (size_t)blockIdx.x * blockDim.x + threadIdx.x;
    if (i >= n4) return;
    const float4 v = reinterpret_cast<const float4*>(in)[i];
    const float a[4] = {v.x, v.y, v.z, v.w};
    __half h[4], l[4];
    #pragma unroll
    for (int s = 0; s < 4; ++s) {
        h[s] = __float2half_rn(a[s]);
        l[s] = __float2half_rn(a[s] - __half2float(h[s]));
    }
    reinterpret_cast<__half2*>(oh)[2 * i]     = __halves2half2(h[0], h[1]);
    reinterpret_cast<__half2*>(oh)[2 * i + 1] = __halves2half2(h[2], h[3]);
    reinterpret_cast<__half2*>(ol)[2 * i]     = __halves2half2(l[0], l[1]);
    reinterpret_cast<__half2*>(ol)[2 * i + 1] = __halves2half2(l[2], l[3]);
}

// ---------------------------------------------------------------------------
// Weight transpose + split: W[K][Nreal] f32 -> Wt_hi/lo[Npad][K] fp16
// ---------------------------------------------------------------------------
__global__ __launch_bounds__(256)
void transpose_split(const float* __restrict__ W,
                     __half* __restrict__ Th, __half* __restrict__ Tl,
                     int K, int Nreal)
{
    __shared__ float s[32][33];
    const int n0 = blockIdx.x * 32, k0 = blockIdx.y * 32;
    const int tx = threadIdx.x, ty = threadIdx.y;   // 32 x 8
    #pragma unroll
    for (int i = 0; i < 32; i += 8) {
        const int k = k0 + ty + i, n = n0 + tx;
        s[ty + i][tx] = (n < Nreal) ? W[(size_t)k * Nreal + n] : 0.0f;
    }
    __syncthreads();
    #pragma unroll
    for (int i = 0; i < 32; i += 8) {
        const int n = n0 + ty + i, k = k0 + tx;
        const float v = s[tx][ty + i];
        const __half h = __float2half_rn(v);
        Th[(size_t)n * K + k] = h;
        Tl[(size_t)n * K + k] = __float2half_rn(v - __half2float(h));
    }
}

// ---------------------------------------------------------------------------
// FFMA SGEMM with softplus (delta: K=64)
// ---------------------------------------------------------------------------
__global__ __launch_bounds__(256, 2)
void sgemm_softplus(const float* __restrict__ A, const float* __restrict__ Bm,
                    const float* __restrict__ bias, float* __restrict__ out,
                    int M, int N, int K, int lda, int ldc)
{
    constexpr int BM = 128, BN = 128, BK = 16, TM = 8, TN = 8;
    __shared__ float As[BK][BM];
    __shared__ float Bs[BK][BN];

    const int tid = threadIdx.x;
    const int tx = tid & 15, ty = tid >> 4;
    const int m0 = blockIdx.y * BM, n0 = blockIdx.x * BN;
    const int arow = tid >> 2, acol = (tid & 3) * 4;
    const int brow = tid >> 5, bcol = (tid & 31) * 4;

    float acc[TM][TN] = {};
    for (int k0 = 0; k0 < K; k0 += BK) {
        #pragma unroll
        for (int p = 0; p < 2; ++p) {
            int r = arow + p * 64;
            float4 v = *(const float4*)(A + (size_t)(m0 + r) * lda + k0 + acol);
            As[acol + 0][r] = v.x; As[acol + 1][r] = v.y;
            As[acol + 2][r] = v.z; As[acol + 3][r] = v.w;
        }
        #pragma unroll
        for (int p = 0; p < 2; ++p) {
            int r = brow + p * 8;
            *(float4*)(&Bs[r][bcol]) = *(const float4*)(Bm + (size_t)(k0 + r) * N + n0 + bcol);
        }
        __syncthreads();
        #pragma unroll
        for (int kk = 0; kk < BK; ++kk) {
            float4 a0 = *(const float4*)(&As[kk][ty * TM]);
            float4 a1 = *(const float4*)(&As[kk][ty * TM + 4]);
            float4 b0 = *(const float4*)(&Bs[kk][tx * TN]);
            float4 b1 = *(const float4*)(&Bs[kk][tx * TN + 4]);
            float ar[TM] = {a0.x, a0.y, a0.z, a0.w, a1.x, a1.y, a1.z, a1.w};
            float br[TN] = {b0.x, b0.y, b0.z, b0.w, b1.x, b1.y, b1.z, b1.w};
            #pragma unroll
            for (int i = 0; i < TM; ++i)
                #pragma unroll
                for (int j = 0; j < TN; ++j)
                    acc[i][j] = fmaf(ar[i], br[j], acc[i][j]);
        }
        __syncthreads();
    }
    const int row0 = m0 + ty * TM, col0 = n0 + tx * TN;
    #pragma unroll
    for (int i = 0; i < TM; ++i)
        #pragma unroll
        for (int j = 0; j < TN; ++j) {
            float v = acc[i][j] + bias[col0 + j];
            out[(size_t)(row0 + i) * ldc + col0 + j] =
                (v > 20.0f) ? v : log1pf(__expf(v));
        }
}

// ---------------------------------------------------------------------------
// Selective scan: one warp per (b, d); 2 states/lane; fused gating epilogue.
// Writes y as fp16 hi/lo (consumed only by G5 HMMA GEMM).
// ---------------------------------------------------------------------------
__global__ __launch_bounds__(256)
void scan_kernel(const float* __restrict__ A_log, const float* __restrict__ Dp)
{
    const int b    = blockIdx.y;
    const int warp = threadIdx.x >> 5;
    const int lane = threadIdx.x & 31;
    const int d    = blockIdx.x * 8 + warp;

    const float A0 = -__expf(A_log[d * DS + 2 * lane]);
    const float A1 = -__expf(A_log[d * DS + 2 * lane + 1]);
    const float dp = Dp[d];

    const float* dlt = g_delta + (size_t)b * Ls * DI + d;
    const float* xsp = g_xs    + (size_t)b * Ls * DI + d;
    const float* rsp = g_rsil  + (size_t)b * Ls * DI + d;
    const float* csp = g_xdbl  + (size_t)b * Ls * ND + 2 * DS + d;
    const float* bsp = g_xdbl  + (size_t)b * Ls * ND + DS;
    __half* yh = g_yhi + (size_t)b * Ls * DI + d;
    __half* yl = g_ylo + (size_t)b * Ls * DI + d;

    float h0 = 0.0f, h1 = 0.0f;
    for (int l = 0; l < Ls; ++l) {
        const float  delta_t = dlt[(size_t)l * DI];
        const float  x_t     = xsp[(size_t)l * DI];
        const float  c_t     = csp[(size_t)l * ND];
        const float2 bb      = *(const float2*)(bsp + (size_t)l * ND + 2 * lane);

        const float dA0 = __expf(delta_t * A0);
        const float dA1 = __expf(delta_t * A1);
        const float dx  = delta_t * x_t;
        h0 = fmaf(dA0, h0, dx * bb.x);
        h1 = fmaf(dA1, h1, dx * bb.y);

        float s = h0 + h1;
        #pragma unroll
        for (int o = 16; o; o >>= 1) s += __shfl_xor_sync(0xffffffffu, s, o);

        if (lane == 0) {
            float y = c_t * s;
            y = (y + x_t * dp) * rsp[(size_t)l * DI];
            const __half h = __float2half_rn(y);
            yh[(size_t)l * DI] = h;
            yl[(size_t)l * DI] = __float2half_rn(y - __half2float(h));
        }
    }
}

// ---------------------------------------------------------------------------
// LayerNorm in place (rows of DM)
// ---------------------------------------------------------------------------
__global__ __launch_bounds__(256)
void ln_kernel(float* __restrict__ io, const float* __restrict__ gamma,
               const float* __restrict__ beta)
{
    const int row = blockIdx.x;
    const int t = threadIdx.x;
    float* p = io + (size_t)row * DM;

    float4 v = reinterpret_cast<float4*>(p)[t];
    __shared__ float sred[8];

    float s = v.x + v.y + v.z + v.w;
    #pragma unroll
    for (int o = 16; o; o >>= 1) s += __shfl_xor_sync(0xffffffffu, s, o);
    if ((t & 31) == 0) sred[t >> 5] = s;
    __syncthreads();
    float mean = 0.0f;
    #pragma unroll
    for (int i = 0; i < 8; ++i) mean += sred[i];
    mean *= (1.0f / DM);
    __syncthreads();

    const float d0 = v.x - mean, d1 = v.y - mean, d2 = v.z - mean, d3 = v.w - mean;
    float q = d0 * d0 + d1 * d1 + d2 * d2 + d3 * d3;
    #pragma unroll
    for (int o = 16; o; o >>= 1) q += __shfl_xor_sync(0xffffffffu, q, o);
    if ((t & 31) == 0) sred[t >> 5] = q;
    __syncthreads();
    float var = 0.0f;
    #pragma unroll
    for (int i = 0; i < 8; ++i) var += sred[i];
    var *= (1.0f / DM);
    const float rstd = rsqrtf(var + 1e-5f);

    const float4 g  = reinterpret_cast<const float4*>(gamma)[t];
    const float4 bt = reinterpret_cast<const float4*>(beta)[t];
    float4 o4;
    o4.x = g.x * d0 * rstd + bt.x;
    o4.y = g.y * d1 * rstd + bt.y;
    o4.z = g.z * d2 * rstd + bt.z;
    o4.w = g.w * d3 * rstd + bt.w;
    reinterpret_cast<float4*>(p)[t] = o4;
}

// ---------------------------------------------------------------------------
// Launch
// ---------------------------------------------------------------------------
extern "C" void kernel_launch(void* const* d_in, const int* in_sizes, int n_in,
                              void* d_out, int out_size)
{
    (void)in_sizes; (void)n_in; (void)out_size;
    const float* x     = (const float*)d_in[0];
    const float* Wi    = (const float*)d_in[1];
    const float* bi    = (const float*)d_in[2];
    const float* Wx    = (const float*)d_in[3];
    const float* bx    = (const float*)d_in[4];
    const float* Wdt   = (const float*)d_in[5];
    const float* bdt   = (const float*)d_in[6];
    const float* A_log = (const float*)d_in[7];
    const float* Dp    = (const float*)d_in[8];
    const float* Wo    = (const float*)d_in[9];
    const float* bo    = (const float*)d_in[10];
    const float* gamma = (const float*)d_in[11];
    const float* beta  = (const float*)d_in[12];
    float* out = (float*)d_out;

    float *xs, *rsil, *xdbl, *delta;
    __half *xhi, *xlo, *xshi, *xslo, *yhi, *ylo;
    __half *Wihi, *Wilo, *Wxhi, *Wxlo, *Wohi, *Wolo;
    cudaGetSymbolAddress((void**)&xs,    g_xs);
    cudaGetSymbolAddress((void**)&rsil,  g_rsil);
    cudaGetSymbolAddress((void**)&xdbl,  g_xdbl);
    cudaGetSymbolAddress((void**)&delta, g_delta);
    cudaGetSymbolAddress((void**)&xhi,   g_xhi);
    cudaGetSymbolAddress((void**)&xlo,   g_xlo);
    cudaGetSymbolAddress((void**)&xshi,  g_xshi);
    cudaGetSymbolAddress((void**)&xslo,  g_xslo);
    cudaGetSymbolAddress((void**)&yhi,   g_yhi);
    cudaGetSymbolAddress((void**)&ylo,   g_ylo);
    cudaGetSymbolAddress((void**)&Wihi,  g_Wihi);
    cudaGetSymbolAddress((void**)&Wilo,  g_Wilo);
    cudaGetSymbolAddress((void**)&Wxhi,  g_Wxhi);
    cudaGetSymbolAddress((void**)&Wxlo,  g_Wxlo);
    cudaGetSymbolAddress((void**)&Wohi,  g_Wohi);
    cudaGetSymbolAddress((void**)&Wolo,  g_Wolo);

    cudaFuncSetAttribute(hmma_gemm<EPI_G1>, cudaFuncAttributeMaxDynamicSharedMemorySize, HT_SMEM);
    cudaFuncSetAttribute(hmma_gemm<EPI_G2>, cudaFuncAttributeMaxDynamicSharedMemorySize, HT_SMEM);
    cudaFuncSetAttribute(hmma_gemm<EPI_G5>, cudaFuncAttributeMaxDynamicSharedMemorySize, HT_SMEM);

    // ---- prep: split x, transpose+split weights
    {
        const size_t n4 = (size_t)MR * DM / 4;
        convert_split<<<(unsigned)((n4 + 255) / 256), 256>>>(x, xhi, xlo, n4);
    }
    transpose_split<<<dim3(N1 / 32,  DM / 32), dim3(32, 8)>>>(Wi, Wihi, Wilo, DM, N1);
    transpose_split<<<dim3(NDP / 32, DI / 32), dim3(32, 8)>>>(Wx, Wxhi, Wxlo, DI, ND);
    transpose_split<<<dim3(DM / 32,  DI / 32), dim3(32, 8)>>>(Wo, Wohi, Wolo, DI, DM);

    // ---- G1: x @ Wi + bi -> silu, split xs(+fp16 hi/lo) / silu(res)
    hmma_gemm<EPI_G1><<<dim3(N1 / 128, MR / 64), 256, HT_SMEM>>>(
        xhi, xlo, Wihi, Wilo, bi, xs, rsil, xshi, xslo, nullptr, DM);

    // ---- G2: xs @ Wx + bx -> x_dbl  (17 column blocks cover ND exactly)
    hmma_gemm<EPI_G2><<<dim3(ND / 128, MR / 64), 256, HT_SMEM>>>(
        xshi, xslo, Wxhi, Wxlo, bx, xdbl, nullptr, nullptr, nullptr, nullptr, DI);

    // ---- G3: softplus(d_raw @ Wdt + bdt) (K=64, FFMA)
    sgemm_softplus<<<dim3(DI / 128, MR / 128), 256>>>(
        xdbl, Wdt, bdt, delta, MR, DI, DS, ND, DI);

    // ---- scan + gating (fp16 hi/lo y)
    scan_kernel<<<dim3(DI / 8, Bb), 256>>>(A_log, Dp);

    // ---- G5: y @ Wo + bo + residual
    hmma_gemm<EPI_G5><<<dim3(DM / 128, MR / 64), 256, HT_SMEM>>>(
        yhi, ylo, Wohi, Wolo, bo, out, nullptr, nullptr, nullptr, x, DI);

    // ---- LayerNorm
    ln_kernel<<<MR, 256>>>(out, gamma, beta);
}